// round 14
// baseline (speedup 1.0000x reference)
#include <cuda_runtime.h>
#include <cuda_fp16.h>
#include <math.h>
#include <stdint.h>

// B=64, T=20, N=100, F=64, H=256
#define Bz 64
#define Tz 20
#define Nz 100
#define Fz 64
#define Hz 256
#define ELEMS (64UL*20UL*100UL*256UL)   // 32,768,000

__device__ float g_h[ELEMS];
__device__ float g_g[ELEMS];           // reused as split buffer #2
__device__ float g_q[ELEMS];
__device__ float g_k[ELEMS];
__device__ float g_v[ELEMS];
__device__ uint8_t g_asplit[ELEMS * 4];  // split buffer #1
#define WPACK_STRIDE 262144
__device__ uint8_t g_wpack[7 * WPACK_STRIDE];

// ---------------------------------------------------------------------------
// helpers
// ---------------------------------------------------------------------------
__device__ __forceinline__ uint32_t smem_u32(const void* p) {
    uint32_t a;
    asm("{ .reg .u64 t; cvta.to.shared.u64 t, %1; cvt.u32.u64 %0, t; }" : "=r"(a) : "l"(p));
    return a;
}
__device__ __forceinline__ void ldsm_x4(uint32_t* r, uint32_t addr) {
    asm volatile("ldmatrix.sync.aligned.m8n8.x4.shared.b16 {%0,%1,%2,%3}, [%4];"
                 : "=r"(r[0]), "=r"(r[1]), "=r"(r[2]), "=r"(r[3]) : "r"(addr));
}
__device__ __forceinline__ void ldsm_x2(uint32_t* r, uint32_t addr) {
    asm volatile("ldmatrix.sync.aligned.m8n8.x2.shared.b16 {%0,%1}, [%2];"
                 : "=r"(r[0]), "=r"(r[1]) : "r"(addr));
}
__device__ __forceinline__ void mma16816(float* d, const uint32_t* a, const uint32_t* b) {
    asm volatile(
        "mma.sync.aligned.m16n8k16.row.col.f32.f16.f16.f32 "
        "{%0,%1,%2,%3}, {%4,%5,%6,%7}, {%8,%9}, {%0,%1,%2,%3};"
        : "+f"(d[0]), "+f"(d[1]), "+f"(d[2]), "+f"(d[3])
        : "r"(a[0]), "r"(a[1]), "r"(a[2]), "r"(a[3]), "r"(b[0]), "r"(b[1]));
}
__device__ __forceinline__ void split_h2(float x, float y, uint32_t& hi, uint32_t& lo) {
    __half h0 = __float2half(x), h1 = __float2half(y);
    __half l0 = __float2half(x - __half2float(h0));
    __half l1 = __float2half(y - __half2float(h1));
    __half2 hp = make_half2(h0, h1), lp = make_half2(l0, l1);
    hi = *(uint32_t*)&hp; lo = *(uint32_t*)&lp;
}
__device__ __forceinline__ void cp16(uint32_t saddr, const void* gaddr) {
    asm volatile("cp.async.cg.shared.global [%0], [%1], 16;" :: "r"(saddr), "l"(gaddr));
}
// packed fp32 pair helpers (sm_100-family f32x2 ops)
__device__ __forceinline__ unsigned long long pack_ff(float v) {
    unsigned long long p;
    asm("mov.b64 %0, {%1, %1};" : "=l"(p) : "f"(v));
    return p;
}
__device__ __forceinline__ void fma2(unsigned long long& d, unsigned long long a,
                                     unsigned long long b) {
    asm("fma.rn.f32x2 %0, %1, %2, %0;" : "+l"(d) : "l"(a), "l"(b));
}
__device__ __forceinline__ void unpack_ff(unsigned long long p, float& x, float& y) {
    asm("mov.b64 {%0, %1}, %2;" : "=f"(x), "=f"(y) : "l"(p));
}

// ---------------------------------------------------------------------------
// Packing: all 7 weight matrices in one launch
// ---------------------------------------------------------------------------
struct W7 { const float* w[7]; };

__global__ void pack_w_all(W7 ws, uint8_t* __restrict__ dst) {
    int mat = blockIdx.y;
    int K = (mat == 0) ? 64 : 256;
    int i = blockIdx.x * blockDim.x + threadIdx.x;
    if (i >= K * 256) return;
    int k = i >> 8, n = i & 255;
    float v = ws.w[mat][i];
    __half h = __float2half(v);
    __half l = __float2half(v - __half2float(h));
    int nblk = n >> 7, rn = n & 127, chunk = k >> 6, kl = k & 63;
    int ncK = K >> 6;
    uint32_t boff = (uint32_t)(rn * 128 + ((((kl >> 3) ^ (rn & 7))) << 4) + (kl & 7) * 2);
    uint8_t* tile = dst + (size_t)mat * WPACK_STRIDE + (size_t)(nblk * ncK + chunk) * 32768;
    *(__half*)(tile + boff) = h;
    *(__half*)(tile + 16384 + boff) = l;
}

// ---------------------------------------------------------------------------
// Pipelined warp-MMA fp16x3 GEMM: 128x256 CTA tile, 512 thr (16 warps)
// ---------------------------------------------------------------------------
#define STG_B 98304
#define SMEM_GEMM (1024 + 2 * STG_B)

__device__ __forceinline__ void gemm_core(
    const uint8_t* __restrict__ As, const uint8_t* __restrict__ Wp,
    const float* __restrict__ bias, const float* res,
    float* out, uint8_t* out_split, int K, int do_relu, int mtile)
{
    extern __shared__ char sm[];
    const uint32_t sbase = smem_u32(sm);
    const int tid = threadIdx.x;
    const int warp = tid >> 5, lane = tid & 31;
    const int m0 = mtile * 128;
    const int nc = K >> 6;

    if (tid < 256) ((float*)sm)[tid] = bias[tid];

    const uint8_t* Abase = As + (size_t)mtile * (nc * 32768);

    auto issue = [&](int c) {
        uint32_t sa = sbase + 1024 + (c & 1) * STG_B;
        const uint8_t* ga = Abase + (size_t)c * 32768 + tid * 16;
        const uint8_t* gb0 = Wp + (size_t)c * 32768 + tid * 16;
        const uint8_t* gb1 = Wp + (size_t)(nc + c) * 32768 + tid * 16;
        #pragma unroll
        for (int i = 0; i < 4; i++) cp16(sa + tid * 16 + i * 8192, ga + i * 8192);
        #pragma unroll
        for (int i = 0; i < 4; i++) cp16(sa + 32768 + tid * 16 + i * 8192, gb0 + i * 8192);
        #pragma unroll
        for (int i = 0; i < 4; i++) cp16(sa + 65536 + tid * 16 + i * 8192, gb1 + i * 8192);
        asm volatile("cp.async.commit_group;" ::: "memory");
    };

    float acc[4][4][4] = {};
    const int wm = warp >> 3, wn = warp & 7;
    const int m_base = wm * 64, n_base = wn * 32;
    const int amat = lane >> 3, ar = lane & 7;
    const int arow_b = m_base + (amat & 1) * 8 + ar;
    const int asel = amat >> 1;
    const int l16 = lane & 15;
    const int bmat = l16 >> 3, br = l16 & 7;
    const uint32_t bofs_base = 32768 + (uint32_t)(wn >> 2) * 32768;
    const int brow_loc = (wn & 3) * 32;

    issue(0);
    for (int c = 0; c < nc; c++) {
        if (c + 1 < nc) {
            issue(c + 1);
            asm volatile("cp.async.wait_group 1;" ::: "memory");
        } else {
            asm volatile("cp.async.wait_group 0;" ::: "memory");
        }
        __syncthreads();
        const uint32_t sb = sbase + 1024 + (c & 1) * STG_B;

        #pragma unroll
        for (int ks = 0; ks < 4; ks++) {
            uint32_t bh[4][2], bl[4][2];
            #pragma unroll
            for (int nt = 0; nt < 4; nt++) {
                int brow = brow_loc + nt * 8 + br;
                uint32_t boffs = (uint32_t)(brow * 128 + (((ks * 2 + bmat) ^ (brow & 7)) << 4));
                ldsm_x2(bh[nt], sb + bofs_base + boffs);
                ldsm_x2(bl[nt], sb + bofs_base + 16384 + boffs);
            }
            #pragma unroll
            for (int mt = 0; mt < 4; mt++) {
                int arow = arow_b + mt * 16;
                uint32_t aoffs = (uint32_t)(arow * 128 + (((ks * 2 + asel) ^ (arow & 7)) << 4));
                uint32_t ah[4], al[4];
                ldsm_x4(ah, sb + aoffs);
                ldsm_x4(al, sb + 16384 + aoffs);
                #pragma unroll
                for (int nt = 0; nt < 4; nt++) {
                    mma16816(acc[mt][nt], ah, bh[nt]);
                    mma16816(acc[mt][nt], ah, bl[nt]);
                    mma16816(acc[mt][nt], al, bh[nt]);
                }
            }
        }
        __syncthreads();
    }

    const float* bias_s = (const float*)sm;
    const int g = lane >> 2, tc = lane & 3;
    #pragma unroll
    for (int mt = 0; mt < 4; mt++) {
        int rl0 = m_base + mt * 16 + g;
        #pragma unroll
        for (int nt = 0; nt < 4; nt++) {
            int cl = n_base + nt * 8 + tc * 2;
            float b0 = bias_s[cl], b1 = bias_s[cl + 1];
            float2 o0, o1;
            o0.x = acc[mt][nt][0] + b0; o0.y = acc[mt][nt][1] + b1;
            o1.x = acc[mt][nt][2] + b0; o1.y = acc[mt][nt][3] + b1;
            if (do_relu) {
                o0.x = fmaxf(o0.x, 0.f); o0.y = fmaxf(o0.y, 0.f);
                o1.x = fmaxf(o1.x, 0.f); o1.y = fmaxf(o1.y, 0.f);
            }
            size_t i0 = (size_t)(m0 + rl0) * 256 + cl;
            size_t i1 = (size_t)(m0 + rl0 + 8) * 256 + cl;
            if (res) {
                float2 rv0 = *(const float2*)&res[i0];
                float2 rv1 = *(const float2*)&res[i1];
                o0.x += rv0.x; o0.y += rv0.y;
                o1.x += rv1.x; o1.y += rv1.y;
            }
            if (out_split) {
                int chunk = cl >> 6, kc = (cl >> 3) & 7, inner = (cl & 7) * 2;
                uint8_t* block = out_split + (size_t)(mtile * 4 + chunk) * 32768;
                uint32_t hi, lo;
                int r = rl0;
                uint32_t boff = (uint32_t)(r * 128 + ((kc ^ (r & 7)) << 4) + inner);
                split_h2(o0.x, o0.y, hi, lo);
                *(uint32_t*)(block + boff) = hi;
                *(uint32_t*)(block + 16384 + boff) = lo;
                r = rl0 + 8;
                boff = (uint32_t)(r * 128 + ((kc ^ (r & 7)) << 4) + inner);
                split_h2(o1.x, o1.y, hi, lo);
                *(uint32_t*)(block + boff) = hi;
                *(uint32_t*)(block + 16384 + boff) = lo;
            } else {
                *(float2*)&out[i0] = o0;
                *(float2*)&out[i1] = o1;
            }
        }
    }
}

__global__ __launch_bounds__(512)
void mma_gemm(const uint8_t* __restrict__ As, const uint8_t* __restrict__ Wp,
              const float* __restrict__ bias, const float* res,
              float* out, uint8_t* out_split, int K, int do_relu) {
    gemm_core(As, Wp, bias, res, out, out_split, K, do_relu, blockIdx.x);
}

__global__ __launch_bounds__(512)
void qkv_gemm(const uint8_t* __restrict__ As, const uint8_t* __restrict__ WpBase,
              const float* __restrict__ bq, const float* __restrict__ bk,
              const float* __restrict__ bv,
              float* oq, float* ok, float* ov) {
    int mat = blockIdx.y;
    const uint8_t* Wp = WpBase + (size_t)(3 + mat) * WPACK_STRIDE;
    const float* bias = (mat == 0) ? bq : ((mat == 1) ? bk : bv);
    float* out = (mat == 0) ? oq : ((mat == 1) ? ok : ov);
    gemm_core(As, Wp, bias, nullptr, out, nullptr, 256, 0, blockIdx.x);
}

// ---------------------------------------------------------------------------
// GEMM 128x256 tile + fused LayerNorm epilogue (Wp projection only).
// ---------------------------------------------------------------------------
#define GHDR 4096
#define SMEM_GLN (GHDR + 2 * STG_B)

__global__ __launch_bounds__(512)
void gemm_ln(const uint8_t* __restrict__ As, const uint8_t* __restrict__ Wp,
             const float* __restrict__ bias,
             const float* __restrict__ gamma, const float* __restrict__ beta,
             float* __restrict__ out) {
    extern __shared__ char sm[];
    const uint32_t sbase = smem_u32(sm);
    const int tid = threadIdx.x;
    const int warp = tid >> 5, lane = tid & 31;
    const int mtile = blockIdx.x;
    const int m0 = mtile * 128;
    const int nc = 4;

    if (tid < 256) ((float*)sm)[tid] = bias[tid];
    if (tid >= 256) {
        int t2 = tid - 256;
        ((float*)(sm + 1024))[t2] = gamma[t2];
        ((float*)(sm + 2048))[t2] = beta[t2];
    }

    const uint8_t* Abase = As + (size_t)mtile * (nc * 32768);

    auto issue = [&](int c) {
        uint32_t sa = sbase + GHDR + (c & 1) * STG_B;
        const uint8_t* ga = Abase + (size_t)c * 32768 + tid * 16;
        const uint8_t* gb0 = Wp + (size_t)c * 32768 + tid * 16;
        const uint8_t* gb1 = Wp + (size_t)(nc + c) * 32768 + tid * 16;
        #pragma unroll
        for (int i = 0; i < 4; i++) cp16(sa + tid * 16 + i * 8192, ga + i * 8192);
        #pragma unroll
        for (int i = 0; i < 4; i++) cp16(sa + 32768 + tid * 16 + i * 8192, gb0 + i * 8192);
        #pragma unroll
        for (int i = 0; i < 4; i++) cp16(sa + 65536 + tid * 16 + i * 8192, gb1 + i * 8192);
        asm volatile("cp.async.commit_group;" ::: "memory");
    };

    float acc[4][4][4] = {};
    const int wm = warp >> 3, wn = warp & 7;
    const int m_base = wm * 64, n_base = wn * 32;
    const int amat = lane >> 3, ar = lane & 7;
    const int arow_b = m_base + (amat & 1) * 8 + ar;
    const int asel = amat >> 1;
    const int l16 = lane & 15;
    const int bmat = l16 >> 3, br = l16 & 7;
    const uint32_t bofs_base = 32768 + (uint32_t)(wn >> 2) * 32768;
    const int brow_loc = (wn & 3) * 32;

    issue(0);
    for (int c = 0; c < nc; c++) {
        if (c + 1 < nc) {
            issue(c + 1);
            asm volatile("cp.async.wait_group 1;" ::: "memory");
        } else {
            asm volatile("cp.async.wait_group 0;" ::: "memory");
        }
        __syncthreads();
        const uint32_t sb = sbase + GHDR + (c & 1) * STG_B;

        #pragma unroll
        for (int ks = 0; ks < 4; ks++) {
            uint32_t bh[4][2], bl[4][2];
            #pragma unroll
            for (int nt = 0; nt < 4; nt++) {
                int brow = brow_loc + nt * 8 + br;
                uint32_t boffs = (uint32_t)(brow * 128 + (((ks * 2 + bmat) ^ (brow & 7)) << 4));
                ldsm_x2(bh[nt], sb + bofs_base + boffs);
                ldsm_x2(bl[nt], sb + bofs_base + 16384 + boffs);
            }
            #pragma unroll
            for (int mt = 0; mt < 4; mt++) {
                int arow = arow_b + mt * 16;
                uint32_t aoffs = (uint32_t)(arow * 128 + (((ks * 2 + asel) ^ (arow & 7)) << 4));
                uint32_t ah[4], al[4];
                ldsm_x4(ah, sb + aoffs);
                ldsm_x4(al, sb + 16384 + aoffs);
                #pragma unroll
                for (int nt = 0; nt < 4; nt++) {
                    mma16816(acc[mt][nt], ah, bh[nt]);
                    mma16816(acc[mt][nt], ah, bl[nt]);
                    mma16816(acc[mt][nt], al, bh[nt]);
                }
            }
        }
        __syncthreads();
    }

    const float* bias_s = (const float*)sm;
    const int g = lane >> 2, tc = lane & 3;
    float* trans = (float*)(sm + GHDR);
    const int TP = 264;
    #pragma unroll
    for (int mt = 0; mt < 4; mt++) {
        int rl0 = m_base + mt * 16 + g;
        #pragma unroll
        for (int nt = 0; nt < 4; nt++) {
            int cl = n_base + nt * 8 + tc * 2;
            float b0 = bias_s[cl], b1 = bias_s[cl + 1];
            *(float2*)&trans[rl0 * TP + cl] =
                make_float2(acc[mt][nt][0] + b0, acc[mt][nt][1] + b1);
            *(float2*)&trans[(rl0 + 8) * TP + cl] =
                make_float2(acc[mt][nt][2] + b0, acc[mt][nt][3] + b1);
        }
    }
    __syncthreads();
    const float* gamma_s = (const float*)(sm + 1024);
    const float* beta_s  = (const float*)(sm + 2048);
    #pragma unroll
    for (int p = 0; p < 8; p++) {
        int row = p * 16 + warp;
        float4 va = *(float4*)&trans[row * TP + lane * 8];
        float4 vb = *(float4*)&trans[row * TP + lane * 8 + 4];
        float s = va.x + va.y + va.z + va.w + vb.x + vb.y + vb.z + vb.w;
        float q = va.x * va.x + va.y * va.y + va.z * va.z + va.w * va.w
                + vb.x * vb.x + vb.y * vb.y + vb.z * vb.z + vb.w * vb.w;
        #pragma unroll
        for (int o = 16; o > 0; o >>= 1) {
            s += __shfl_xor_sync(0xffffffffu, s, o);
            q += __shfl_xor_sync(0xffffffffu, q, o);
        }
        float mu = s * (1.f / 256.f);
        float var = q * (1.f / 256.f) - mu * mu;
        float r = rsqrtf(var + 1e-5f);
        int c0 = lane * 8;
        float4 oa, ob;
        oa.x = (va.x - mu) * r * gamma_s[c0 + 0] + beta_s[c0 + 0];
        oa.y = (va.y - mu) * r * gamma_s[c0 + 1] + beta_s[c0 + 1];
        oa.z = (va.z - mu) * r * gamma_s[c0 + 2] + beta_s[c0 + 2];
        oa.w = (va.w - mu) * r * gamma_s[c0 + 3] + beta_s[c0 + 3];
        ob.x = (vb.x - mu) * r * gamma_s[c0 + 4] + beta_s[c0 + 4];
        ob.y = (vb.y - mu) * r * gamma_s[c0 + 5] + beta_s[c0 + 5];
        ob.z = (vb.z - mu) * r * gamma_s[c0 + 6] + beta_s[c0 + 6];
        ob.w = (vb.w - mu) * r * gamma_s[c0 + 7] + beta_s[c0 + 7];
        size_t ob0 = (size_t)(m0 + row) * 256 + c0;
        *(float4*)&out[ob0] = oa;
        *(float4*)&out[ob0 + 4] = ob;
    }
}

// ---------------------------------------------------------------------------
// SIMT fp32 adjmul -> split image. 2n x 8f per thread, packed f32x2 FMA.
// Per-output accumulation order = sequential m (bit-identical to R13).
// blockIdx.x = bt, blockIdx.y = 64-wide f chunk. 512 threads.
// ---------------------------------------------------------------------------
__global__ __launch_bounds__(512)
void adjmul_split(const float* __restrict__ h, const float* __restrict__ adj,
                  uint8_t* __restrict__ dst, int F_total) {
    extern __shared__ float smf[];
    float* adj_s = smf;            // 100*100
    float* h_s   = smf + 10000;    // 100*64
    const int bt = blockIdx.x;
    const int chunk = blockIdx.y;
    const int f0 = chunk * 64;
    const int ncK = F_total >> 6;
    const float* hp = h + (size_t)bt * Nz * F_total;

    {
        const float4* a4 = (const float4*)adj;
        float4* s4 = (float4*)adj_s;
        for (int i = threadIdx.x; i < 2500; i += 512) s4[i] = a4[i];
        for (int i = threadIdx.x; i < 1600; i += 512) {
            int row = i >> 4, c4 = i & 15;
            ((float4*)h_s)[i] = *(const float4*)&hp[(size_t)row * F_total + f0 + c4 * 4];
        }
    }
    __syncthreads();

    const int fl = threadIdx.x & 7;        // 8 f-lanes x 8 floats = 64 f
    const int nl = threadIdx.x >> 3;       // 64 groups x 2 n rows
    const int n0 = nl * 2;
    if (n0 >= Nz) return;
    const ulonglong2* h2v = (const ulonglong2*)h_s;   // 16 per row (64 floats)
    const float* ar0 = adj_s + (size_t)n0 * Nz;
    const float* ar1 = ar0 + Nz;

    unsigned long long acc0[4] = {0ull, 0ull, 0ull, 0ull};
    unsigned long long acc1[4] = {0ull, 0ull, 0ull, 0ull};

    #pragma unroll 4
    for (int m = 0; m < Nz; m++) {
        unsigned long long w0p = pack_ff(ar0[m]);
        unsigned long long w1p = pack_ff(ar1[m]);
        ulonglong2 ha = h2v[m * 16 + fl * 2];
        ulonglong2 hb = h2v[m * 16 + fl * 2 + 1];
        fma2(acc0[0], w0p, ha.x); fma2(acc0[1], w0p, ha.y);
        fma2(acc0[2], w0p, hb.x); fma2(acc0[3], w0p, hb.y);
        fma2(acc1[0], w1p, ha.x); fma2(acc1[1], w1p, ha.y);
        fma2(acc1[2], w1p, hb.x); fma2(acc1[3], w1p, hb.y);
    }

    // each thread writes one full 16B line (8 halves) per row, hi and lo
    unsigned long long* accs[2] = {acc0, acc1};
    #pragma unroll
    for (int r = 0; r < 2; r++) {
        int mg = bt * Nz + n0 + r;
        int mtile = mg >> 7, row = mg & 127;
        uint8_t* block = dst + (size_t)(mtile * ncK + chunk) * 32768;
        uint32_t boff = (uint32_t)(row * 128 + ((fl ^ (row & 7)) << 4));
        uint4 hiv, lov;
        float x, y;
        unpack_ff(accs[r][0], x, y); split_h2(x, y, hiv.x, lov.x);
        unpack_ff(accs[r][1], x, y); split_h2(x, y, hiv.y, lov.y);
        unpack_ff(accs[r][2], x, y); split_h2(x, y, hiv.z, lov.z);
        unpack_ff(accs[r][3], x, y); split_h2(x, y, hiv.w, lov.w);
        *(uint4*)(block + boff) = hiv;
        *(uint4*)(block + 16384 + boff) = lov;
    }
}

// ---------------------------------------------------------------------------
// Temporal attention; attn@v phase on packed f32x2 FMA; split-image output.
// ---------------------------------------------------------------------------
#define QS 268

__global__ __launch_bounds__(512)
void attn_kernel(const float* __restrict__ q, const float* __restrict__ k,
                 const float* __restrict__ v, uint8_t* __restrict__ dst) {
    extern __shared__ float smf[];
    float* q_s = smf;
    float* k_s = q_s + Tz * QS;
    float* v_s = k_s + Tz * QS;
    float* p_s = v_s + Tz * QS;

    const int b = blockIdx.x / Nz;
    const int n = blockIdx.x % Nz;
    const size_t base = ((size_t)b * Tz * Nz + n) * Hz;
    const size_t tstride = (size_t)Nz * Hz;

    for (int i = threadIdx.x; i < Tz * Hz; i += blockDim.x) {
        int t = i >> 8; int hh = i & 255;
        q_s[t * QS + hh] = q[base + t * tstride + hh];
        k_s[t * QS + hh] = k[base + t * tstride + hh];
        v_s[t * QS + hh] = v[base + t * tstride + hh];
    }
    __syncthreads();

    if (threadIdx.x < Tz * Tz) {
        int t = threadIdx.x / Tz, s = threadIdx.x % Tz;
        const float4* q4 = (const float4*)(q_s + t * QS);
        const float4* k4 = (const float4*)(k_s + s * QS);
        float a0 = 0.f, a1 = 0.f;
        #pragma unroll 8
        for (int c = 0; c < 64; c += 2) {
            float4 qa = q4[c], ka = k4[c];
            float4 qb = q4[c + 1], kb = k4[c + 1];
            a0 += qa.x * ka.x + qa.y * ka.y + qa.z * ka.z + qa.w * ka.w;
            a1 += qb.x * kb.x + qb.y * kb.y + qb.z * kb.z + qb.w * kb.w;
        }
        p_s[t * 21 + s] = (a0 + a1) * 0.0625f;
    }
    __syncthreads();

    if (threadIdx.x < Tz) {
        int t = threadIdx.x;
        float mx = -1e30f;
        #pragma unroll
        for (int s = 0; s < Tz; s++) mx = fmaxf(mx, p_s[t * 21 + s]);
        float sum = 0.f;
        #pragma unroll
        for (int s = 0; s < Tz; s++) {
            float e = expf(p_s[t * 21 + s] - mx);
            p_s[t * 21 + s] = e; sum += e;
        }
        float inv = 1.f / sum;
        #pragma unroll
        for (int s = 0; s < Tz; s++) p_s[t * 21 + s] *= inv;
    }
    __syncthreads();

    for (int u = threadIdx.x; u < Tz * 32; u += 512) {
        int t = u >> 5, hgrp = u & 31;
        unsigned long long acc[4] = {0ull, 0ull, 0ull, 0ull};
        #pragma unroll
        for (int s = 0; s < Tz; s++) {
            unsigned long long pp = pack_ff(p_s[t * 21 + s]);
            const ulonglong2* vv = (const ulonglong2*)(v_s + s * QS + hgrp * 8);
            ulonglong2 va = vv[0], vb = vv[1];
            fma2(acc[0], pp, va.x); fma2(acc[1], pp, va.y);
            fma2(acc[2], pp, vb.x); fma2(acc[3], pp, vb.y);
        }
        int mg = b * Tz * Nz + t * Nz + n;
        int mtile = mg >> 7, row = mg & 127;
        int chunk = hgrp >> 3, kc = hgrp & 7;
        uint8_t* block = dst + (size_t)(mtile * 4 + chunk) * 32768;
        uint32_t boff = (uint32_t)(row * 128 + ((kc ^ (row & 7)) << 4));
        uint4 hiv, lov;
        float x, y;
        unpack_ff(acc[0], x, y); split_h2(x, y, hiv.x, lov.x);
        unpack_ff(acc[1], x, y); split_h2(x, y, hiv.y, lov.y);
        unpack_ff(acc[2], x, y); split_h2(x, y, hiv.z, lov.z);
        unpack_ff(acc[3], x, y); split_h2(x, y, hiv.w, lov.w);
        *(uint4*)(block + boff) = hiv;
        *(uint4*)(block + 16384 + boff) = lov;
    }
}

// ---------------------------------------------------------------------------
// launch
// ---------------------------------------------------------------------------
extern "C" void kernel_launch(void* const* d_in, const int* in_sizes, int n_in,
                              void* d_out, int out_size) {
    const float* x    = (const float*)d_in[0];
    const float* adj  = (const float*)d_in[1];
    const float* W0   = (const float*)d_in[2];
    const float* b0   = (const float*)d_in[3];
    const float* W1   = (const float*)d_in[4];
    const float* b1   = (const float*)d_in[5];
    const float* W2   = (const float*)d_in[6];
    const float* b2   = (const float*)d_in[7];
    const float* Wq   = (const float*)d_in[8];
    const float* bq   = (const float*)d_in[9];
    const float* Wk   = (const float*)d_in[10];
    const float* bk   = (const float*)d_in[11];
    const float* Wv   = (const float*)d_in[12];
    const float* bv   = (const float*)d_in[13];
    const float* Wp   = (const float*)d_in[14];
    const float* bp   = (const float*)d_in[15];
    const float* gamma = (const float*)d_in[16];
    const float* beta  = (const float*)d_in[17];
    float* out = (float*)d_out;

    float *ph, *pq, *pk, *pv, *pg;
    uint8_t *wp, *as1;
    cudaGetSymbolAddress((void**)&ph, g_h);
    cudaGetSymbolAddress((void**)&pg, g_g);
    cudaGetSymbolAddress((void**)&pq, g_q);
    cudaGetSymbolAddress((void**)&pk, g_k);
    cudaGetSymbolAddress((void**)&pv, g_v);
    cudaGetSymbolAddress((void**)&wp, g_wpack);
    cudaGetSymbolAddress((void**)&as1, g_asplit);
    uint8_t* as2 = (uint8_t*)pg;

    const int smem_adj  = (10000 + Nz * 64) * 4;          // 65.6 KB
    const int smem_attn = (3 * Tz * QS + Tz * 21) * 4;    // ~66 KB
    cudaFuncSetAttribute(adjmul_split, cudaFuncAttributeMaxDynamicSharedMemorySize, smem_adj);
    cudaFuncSetAttribute(attn_kernel,  cudaFuncAttributeMaxDynamicSharedMemorySize, smem_attn);
    cudaFuncSetAttribute(mma_gemm,     cudaFuncAttributeMaxDynamicSharedMemorySize, SMEM_GEMM);
    cudaFuncSetAttribute(qkv_gemm,     cudaFuncAttributeMaxDynamicSharedMemorySize, SMEM_GEMM);
    cudaFuncSetAttribute(gemm_ln,      cudaFuncAttributeMaxDynamicSharedMemorySize, SMEM_GLN);

    W7 ws;
    ws.w[0] = W0; ws.w[1] = W1; ws.w[2] = W2; ws.w[3] = Wq;
    ws.w[4] = Wk; ws.w[5] = Wv; ws.w[6] = Wp;
    pack_w_all<<<dim3(256, 7), 256>>>(ws, wp);

    const int BT = Bz * Tz;                 // 1280
    const int M = Bz * Tz * Nz;             // 128000
    const int GT = M / 128;                 // 1000

    // GCN layer 0 (F=64 -> H=256)
    adjmul_split<<<dim3(BT, 1), 512, smem_adj>>>(x, adj, as1, Fz);
    mma_gemm<<<GT, 512, SMEM_GEMM>>>(as1, wp + 0 * WPACK_STRIDE, b0, nullptr, ph, nullptr, Fz, 1);
    // GCN layer 1 (residual)
    adjmul_split<<<dim3(BT, 4), 512, smem_adj>>>(ph, adj, as1, Hz);
    mma_gemm<<<GT, 512, SMEM_GEMM>>>(as1, wp + 1 * WPACK_STRIDE, b1, ph, ph, nullptr, Hz, 1);
    // GCN layer 2 (residual) -> split image (feeds QKV)
    adjmul_split<<<dim3(BT, 4), 512, smem_adj>>>(ph, adj, as1, Hz);
    mma_gemm<<<GT, 512, SMEM_GEMM>>>(as1, wp + 2 * WPACK_STRIDE, b2, ph, nullptr, as2, Hz, 1);
    // Q, K, V fused launch
    qkv_gemm<<<dim3(GT, 3), 512, SMEM_GEMM>>>(as2, wp, bq, bk, bv, pq, pk, pv);
    // attention -> split image (feeds Wp GEMM)
    attn_kernel<<<Bz * Nz, 512, smem_attn>>>(pq, pk, pv, as1);
    // output projection + fused LayerNorm -> final output
    gemm_ln<<<GT, 512, SMEM_GLN>>>(as1, wp + 6 * WPACK_STRIDE, bp, gamma, beta, out);
}

// round 17
// speedup vs baseline: 1.2910x; 1.2910x over previous
#include <cuda_runtime.h>
#include <cuda_fp16.h>
#include <math.h>
#include <stdint.h>

// B=64, T=20, N=100, F=64, H=256
#define Bz 64
#define Tz 20
#define Nz 100
#define Fz 64
#define Hz 256
#define ELEMS (64UL*20UL*100UL*256UL)   // 32,768,000

__device__ float g_h[ELEMS];
__device__ float g_g[ELEMS];           // reused as split buffer #2
__device__ float g_q[ELEMS];
__device__ float g_k[ELEMS];
__device__ float g_v[ELEMS];
__device__ uint8_t g_asplit[ELEMS * 4];  // split buffer #1
#define WPACK_STRIDE 262144
__device__ uint8_t g_wpack[7 * WPACK_STRIDE];

// ---------------------------------------------------------------------------
// helpers
// ---------------------------------------------------------------------------
__device__ __forceinline__ uint32_t smem_u32(const void* p) {
    uint32_t a;
    asm("{ .reg .u64 t; cvta.to.shared.u64 t, %1; cvt.u32.u64 %0, t; }" : "=r"(a) : "l"(p));
    return a;
}
__device__ __forceinline__ void ldsm_x4(uint32_t* r, uint32_t addr) {
    asm volatile("ldmatrix.sync.aligned.m8n8.x4.shared.b16 {%0,%1,%2,%3}, [%4];"
                 : "=r"(r[0]), "=r"(r[1]), "=r"(r[2]), "=r"(r[3]) : "r"(addr));
}
__device__ __forceinline__ void ldsm_x2(uint32_t* r, uint32_t addr) {
    asm volatile("ldmatrix.sync.aligned.m8n8.x2.shared.b16 {%0,%1}, [%2];"
                 : "=r"(r[0]), "=r"(r[1]) : "r"(addr));
}
__device__ __forceinline__ void mma16816(float* d, const uint32_t* a, const uint32_t* b) {
    asm volatile(
        "mma.sync.aligned.m16n8k16.row.col.f32.f16.f16.f32 "
        "{%0,%1,%2,%3}, {%4,%5,%6,%7}, {%8,%9}, {%0,%1,%2,%3};"
        : "+f"(d[0]), "+f"(d[1]), "+f"(d[2]), "+f"(d[3])
        : "r"(a[0]), "r"(a[1]), "r"(a[2]), "r"(a[3]), "r"(b[0]), "r"(b[1]));
}
__device__ __forceinline__ void split_h2(float x, float y, uint32_t& hi, uint32_t& lo) {
    __half h0 = __float2half(x), h1 = __float2half(y);
    __half l0 = __float2half(x - __half2float(h0));
    __half l1 = __float2half(y - __half2float(h1));
    __half2 hp = make_half2(h0, h1), lp = make_half2(l0, l1);
    hi = *(uint32_t*)&hp; lo = *(uint32_t*)&lp;
}
__device__ __forceinline__ void cp16(uint32_t saddr, const void* gaddr) {
    asm volatile("cp.async.cg.shared.global [%0], [%1], 16;" :: "r"(saddr), "l"(gaddr));
}

// ---------------------------------------------------------------------------
// Packing: all 7 weight matrices in one launch
// ---------------------------------------------------------------------------
struct W7 { const float* w[7]; };

__global__ void pack_w_all(W7 ws, uint8_t* __restrict__ dst) {
    int mat = blockIdx.y;
    int K = (mat == 0) ? 64 : 256;
    int i = blockIdx.x * blockDim.x + threadIdx.x;
    if (i >= K * 256) return;
    int k = i >> 8, n = i & 255;
    float v = ws.w[mat][i];
    __half h = __float2half(v);
    __half l = __float2half(v - __half2float(h));
    int nblk = n >> 7, rn = n & 127, chunk = k >> 6, kl = k & 63;
    int ncK = K >> 6;
    uint32_t boff = (uint32_t)(rn * 128 + ((((kl >> 3) ^ (rn & 7))) << 4) + (kl & 7) * 2);
    uint8_t* tile = dst + (size_t)mat * WPACK_STRIDE + (size_t)(nblk * ncK + chunk) * 32768;
    *(__half*)(tile + boff) = h;
    *(__half*)(tile + 16384 + boff) = l;
}

// ---------------------------------------------------------------------------
// Pipelined warp-MMA fp16x3 GEMM: 128x256 CTA tile, 512 thr (16 warps)
// ---------------------------------------------------------------------------
#define STG_B 98304
#define SMEM_GEMM (1024 + 2 * STG_B)

__device__ __forceinline__ void gemm_core(
    const uint8_t* __restrict__ As, const uint8_t* __restrict__ Wp,
    const float* __restrict__ bias, const float* res,
    float* out, uint8_t* out_split, int K, int do_relu, int mtile)
{
    extern __shared__ char sm[];
    const uint32_t sbase = smem_u32(sm);
    const int tid = threadIdx.x;
    const int warp = tid >> 5, lane = tid & 31;
    const int m0 = mtile * 128;
    const int nc = K >> 6;

    if (tid < 256) ((float*)sm)[tid] = bias[tid];

    const uint8_t* Abase = As + (size_t)mtile * (nc * 32768);

    auto issue = [&](int c) {
        uint32_t sa = sbase + 1024 + (c & 1) * STG_B;
        const uint8_t* ga = Abase + (size_t)c * 32768 + tid * 16;
        const uint8_t* gb0 = Wp + (size_t)c * 32768 + tid * 16;
        const uint8_t* gb1 = Wp + (size_t)(nc + c) * 32768 + tid * 16;
        #pragma unroll
        for (int i = 0; i < 4; i++) cp16(sa + tid * 16 + i * 8192, ga + i * 8192);
        #pragma unroll
        for (int i = 0; i < 4; i++) cp16(sa + 32768 + tid * 16 + i * 8192, gb0 + i * 8192);
        #pragma unroll
        for (int i = 0; i < 4; i++) cp16(sa + 65536 + tid * 16 + i * 8192, gb1 + i * 8192);
        asm volatile("cp.async.commit_group;" ::: "memory");
    };

    float acc[4][4][4] = {};
    const int wm = warp >> 3, wn = warp & 7;
    const int m_base = wm * 64, n_base = wn * 32;
    const int amat = lane >> 3, ar = lane & 7;
    const int arow_b = m_base + (amat & 1) * 8 + ar;
    const int asel = amat >> 1;
    const int l16 = lane & 15;
    const int bmat = l16 >> 3, br = l16 & 7;
    const uint32_t bofs_base = 32768 + (uint32_t)(wn >> 2) * 32768;
    const int brow_loc = (wn & 3) * 32;

    issue(0);
    for (int c = 0; c < nc; c++) {
        if (c + 1 < nc) {
            issue(c + 1);
            asm volatile("cp.async.wait_group 1;" ::: "memory");
        } else {
            asm volatile("cp.async.wait_group 0;" ::: "memory");
        }
        __syncthreads();
        const uint32_t sb = sbase + 1024 + (c & 1) * STG_B;

        #pragma unroll
        for (int ks = 0; ks < 4; ks++) {
            uint32_t bh[4][2], bl[4][2];
            #pragma unroll
            for (int nt = 0; nt < 4; nt++) {
                int brow = brow_loc + nt * 8 + br;
                uint32_t boffs = (uint32_t)(brow * 128 + (((ks * 2 + bmat) ^ (brow & 7)) << 4));
                ldsm_x2(bh[nt], sb + bofs_base + boffs);
                ldsm_x2(bl[nt], sb + bofs_base + 16384 + boffs);
            }
            #pragma unroll
            for (int mt = 0; mt < 4; mt++) {
                int arow = arow_b + mt * 16;
                uint32_t aoffs = (uint32_t)(arow * 128 + (((ks * 2 + asel) ^ (arow & 7)) << 4));
                uint32_t ah[4], al[4];
                ldsm_x4(ah, sb + aoffs);
                ldsm_x4(al, sb + 16384 + aoffs);
                #pragma unroll
                for (int nt = 0; nt < 4; nt++) {
                    mma16816(acc[mt][nt], ah, bh[nt]);
                    mma16816(acc[mt][nt], ah, bl[nt]);
                    mma16816(acc[mt][nt], al, bh[nt]);
                }
            }
        }
        __syncthreads();
    }

    const float* bias_s = (const float*)sm;
    const int g = lane >> 2, tc = lane & 3;
    #pragma unroll
    for (int mt = 0; mt < 4; mt++) {
        int rl0 = m_base + mt * 16 + g;
        #pragma unroll
        for (int nt = 0; nt < 4; nt++) {
            int cl = n_base + nt * 8 + tc * 2;
            float b0 = bias_s[cl], b1 = bias_s[cl + 1];
            float2 o0, o1;
            o0.x = acc[mt][nt][0] + b0; o0.y = acc[mt][nt][1] + b1;
            o1.x = acc[mt][nt][2] + b0; o1.y = acc[mt][nt][3] + b1;
            if (do_relu) {
                o0.x = fmaxf(o0.x, 0.f); o0.y = fmaxf(o0.y, 0.f);
                o1.x = fmaxf(o1.x, 0.f); o1.y = fmaxf(o1.y, 0.f);
            }
            size_t i0 = (size_t)(m0 + rl0) * 256 + cl;
            size_t i1 = (size_t)(m0 + rl0 + 8) * 256 + cl;
            if (res) {
                float2 rv0 = *(const float2*)&res[i0];
                float2 rv1 = *(const float2*)&res[i1];
                o0.x += rv0.x; o0.y += rv0.y;
                o1.x += rv1.x; o1.y += rv1.y;
            }
            if (out_split) {
                int chunk = cl >> 6, kc = (cl >> 3) & 7, inner = (cl & 7) * 2;
                uint8_t* block = out_split + (size_t)(mtile * 4 + chunk) * 32768;
                uint32_t hi, lo;
                int r = rl0;
                uint32_t boff = (uint32_t)(r * 128 + ((kc ^ (r & 7)) << 4) + inner);
                split_h2(o0.x, o0.y, hi, lo);
                *(uint32_t*)(block + boff) = hi;
                *(uint32_t*)(block + 16384 + boff) = lo;
                r = rl0 + 8;
                boff = (uint32_t)(r * 128 + ((kc ^ (r & 7)) << 4) + inner);
                split_h2(o1.x, o1.y, hi, lo);
                *(uint32_t*)(block + boff) = hi;
                *(uint32_t*)(block + 16384 + boff) = lo;
            } else {
                *(float2*)&out[i0] = o0;
                *(float2*)&out[i1] = o1;
            }
        }
    }
}

__global__ __launch_bounds__(512)
void mma_gemm(const uint8_t* __restrict__ As, const uint8_t* __restrict__ Wp,
              const float* __restrict__ bias, const float* res,
              float* out, uint8_t* out_split, int K, int do_relu) {
    gemm_core(As, Wp, bias, res, out, out_split, K, do_relu, blockIdx.x);
}

// blockIdx.x = mat (0..2), blockIdx.y = mtile — adjacent bids share the A tile
// so the 131MB A-split image is fetched from DRAM once (L2 reuse), not 3x.
__global__ __launch_bounds__(512)
void qkv_gemm(const uint8_t* __restrict__ As, const uint8_t* __restrict__ WpBase,
              const float* __restrict__ bq, const float* __restrict__ bk,
              const float* __restrict__ bv,
              float* oq, float* ok, float* ov) {
    int mat = blockIdx.x;
    const uint8_t* Wp = WpBase + (size_t)(3 + mat) * WPACK_STRIDE;
    const float* bias = (mat == 0) ? bq : ((mat == 1) ? bk : bv);
    float* out = (mat == 0) ? oq : ((mat == 1) ? ok : ov);
    gemm_core(As, Wp, bias, nullptr, out, nullptr, 256, 0, blockIdx.y);
}

// ---------------------------------------------------------------------------
// GEMM 128x256 tile + fused LayerNorm epilogue (Wp projection only).
// ---------------------------------------------------------------------------
#define GHDR 4096
#define SMEM_GLN (GHDR + 2 * STG_B)

__global__ __launch_bounds__(512)
void gemm_ln(const uint8_t* __restrict__ As, const uint8_t* __restrict__ Wp,
             const float* __restrict__ bias,
             const float* __restrict__ gamma, const float* __restrict__ beta,
             float* __restrict__ out) {
    extern __shared__ char sm[];
    const uint32_t sbase = smem_u32(sm);
    const int tid = threadIdx.x;
    const int warp = tid >> 5, lane = tid & 31;
    const int mtile = blockIdx.x;
    const int m0 = mtile * 128;
    const int nc = 4;

    if (tid < 256) ((float*)sm)[tid] = bias[tid];
    if (tid >= 256) {
        int t2 = tid - 256;
        ((float*)(sm + 1024))[t2] = gamma[t2];
        ((float*)(sm + 2048))[t2] = beta[t2];
    }

    const uint8_t* Abase = As + (size_t)mtile * (nc * 32768);

    auto issue = [&](int c) {
        uint32_t sa = sbase + GHDR + (c & 1) * STG_B;
        const uint8_t* ga = Abase + (size_t)c * 32768 + tid * 16;
        const uint8_t* gb0 = Wp + (size_t)c * 32768 + tid * 16;
        const uint8_t* gb1 = Wp + (size_t)(nc + c) * 32768 + tid * 16;
        #pragma unroll
        for (int i = 0; i < 4; i++) cp16(sa + tid * 16 + i * 8192, ga + i * 8192);
        #pragma unroll
        for (int i = 0; i < 4; i++) cp16(sa + 32768 + tid * 16 + i * 8192, gb0 + i * 8192);
        #pragma unroll
        for (int i = 0; i < 4; i++) cp16(sa + 65536 + tid * 16 + i * 8192, gb1 + i * 8192);
        asm volatile("cp.async.commit_group;" ::: "memory");
    };

    float acc[4][4][4] = {};
    const int wm = warp >> 3, wn = warp & 7;
    const int m_base = wm * 64, n_base = wn * 32;
    const int amat = lane >> 3, ar = lane & 7;
    const int arow_b = m_base + (amat & 1) * 8 + ar;
    const int asel = amat >> 1;
    const int l16 = lane & 15;
    const int bmat = l16 >> 3, br = l16 & 7;
    const uint32_t bofs_base = 32768 + (uint32_t)(wn >> 2) * 32768;
    const int brow_loc = (wn & 3) * 32;

    issue(0);
    for (int c = 0; c < nc; c++) {
        if (c + 1 < nc) {
            issue(c + 1);
            asm volatile("cp.async.wait_group 1;" ::: "memory");
        } else {
            asm volatile("cp.async.wait_group 0;" ::: "memory");
        }
        __syncthreads();
        const uint32_t sb = sbase + GHDR + (c & 1) * STG_B;

        #pragma unroll
        for (int ks = 0; ks < 4; ks++) {
            uint32_t bh[4][2], bl[4][2];
            #pragma unroll
            for (int nt = 0; nt < 4; nt++) {
                int brow = brow_loc + nt * 8 + br;
                uint32_t boffs = (uint32_t)(brow * 128 + (((ks * 2 + bmat) ^ (brow & 7)) << 4));
                ldsm_x2(bh[nt], sb + bofs_base + boffs);
                ldsm_x2(bl[nt], sb + bofs_base + 16384 + boffs);
            }
            #pragma unroll
            for (int mt = 0; mt < 4; mt++) {
                int arow = arow_b + mt * 16;
                uint32_t aoffs = (uint32_t)(arow * 128 + (((ks * 2 + asel) ^ (arow & 7)) << 4));
                uint32_t ah[4], al[4];
                ldsm_x4(ah, sb + aoffs);
                ldsm_x4(al, sb + 16384 + aoffs);
                #pragma unroll
                for (int nt = 0; nt < 4; nt++) {
                    mma16816(acc[mt][nt], ah, bh[nt]);
                    mma16816(acc[mt][nt], ah, bl[nt]);
                    mma16816(acc[mt][nt], al, bh[nt]);
                }
            }
        }
        __syncthreads();
    }

    const float* bias_s = (const float*)sm;
    const int g = lane >> 2, tc = lane & 3;
    float* trans = (float*)(sm + GHDR);
    const int TP = 264;
    #pragma unroll
    for (int mt = 0; mt < 4; mt++) {
        int rl0 = m_base + mt * 16 + g;
        #pragma unroll
        for (int nt = 0; nt < 4; nt++) {
            int cl = n_base + nt * 8 + tc * 2;
            float b0 = bias_s[cl], b1 = bias_s[cl + 1];
            *(float2*)&trans[rl0 * TP + cl] =
                make_float2(acc[mt][nt][0] + b0, acc[mt][nt][1] + b1);
            *(float2*)&trans[(rl0 + 8) * TP + cl] =
                make_float2(acc[mt][nt][2] + b0, acc[mt][nt][3] + b1);
        }
    }
    __syncthreads();
    const float* gamma_s = (const float*)(sm + 1024);
    const float* beta_s  = (const float*)(sm + 2048);
    #pragma unroll
    for (int p = 0; p < 8; p++) {
        int row = p * 16 + warp;
        float4 va = *(float4*)&trans[row * TP + lane * 8];
        float4 vb = *(float4*)&trans[row * TP + lane * 8 + 4];
        float s = va.x + va.y + va.z + va.w + vb.x + vb.y + vb.z + vb.w;
        float q = va.x * va.x + va.y * va.y + va.z * va.z + va.w * va.w
                + vb.x * vb.x + vb.y * vb.y + vb.z * vb.z + vb.w * vb.w;
        #pragma unroll
        for (int o = 16; o > 0; o >>= 1) {
            s += __shfl_xor_sync(0xffffffffu, s, o);
            q += __shfl_xor_sync(0xffffffffu, q, o);
        }
        float mu = s * (1.f / 256.f);
        float var = q * (1.f / 256.f) - mu * mu;
        float r = rsqrtf(var + 1e-5f);
        int c0 = lane * 8;
        float4 oa, ob;
        oa.x = (va.x - mu) * r * gamma_s[c0 + 0] + beta_s[c0 + 0];
        oa.y = (va.y - mu) * r * gamma_s[c0 + 1] + beta_s[c0 + 1];
        oa.z = (va.z - mu) * r * gamma_s[c0 + 2] + beta_s[c0 + 2];
        oa.w = (va.w - mu) * r * gamma_s[c0 + 3] + beta_s[c0 + 3];
        ob.x = (vb.x - mu) * r * gamma_s[c0 + 4] + beta_s[c0 + 4];
        ob.y = (vb.y - mu) * r * gamma_s[c0 + 5] + beta_s[c0 + 5];
        ob.z = (vb.z - mu) * r * gamma_s[c0 + 6] + beta_s[c0 + 6];
        ob.w = (vb.w - mu) * r * gamma_s[c0 + 7] + beta_s[c0 + 7];
        size_t ob0 = (size_t)(m0 + row) * 256 + c0;
        *(float4*)&out[ob0] = oa;
        *(float4*)&out[ob0 + 4] = ob;
    }
}

// ---------------------------------------------------------------------------
// SIMT fp32 adjmul -> split image (R13 numerics: sequential m order, 4n x 4f).
// blockIdx.x = bt, blockIdx.y = 64-wide f chunk. 512 threads.
// ---------------------------------------------------------------------------
__global__ __launch_bounds__(512)
void adjmul_split(const float* __restrict__ h, const float* __restrict__ adj,
                  uint8_t* __restrict__ dst, int F_total) {
    extern __shared__ float smf[];
    float* adj_s = smf;            // 100*100
    float* h_s   = smf + 10000;    // 100*64
    const int bt = blockIdx.x;
    const int chunk = blockIdx.y;
    const int f0 = chunk * 64;
    const int ncK = F_total >> 6;
    const float* hp = h + (size_t)bt * Nz * F_total;

    {
        const float4* a4 = (const float4*)adj;
        float4* s4 = (float4*)adj_s;
        for (int i = threadIdx.x; i < 2500; i += 512) s4[i] = a4[i];
        for (int i = threadIdx.x; i < 1600; i += 512) {
            int row = i >> 4, c4 = i & 15;
            ((float4*)h_s)[i] = *(const float4*)&hp[(size_t)row * F_total + f0 + c4 * 4];
        }
    }
    __syncthreads();

    const int fq = threadIdx.x & 15;
    const int nl = threadIdx.x >> 4;
    const int n0 = nl * 4;
    if (n0 >= Nz) return;
    const float4* h4 = (const float4*)h_s;

    float4 a0 = make_float4(0.f, 0.f, 0.f, 0.f), a1 = a0, a2 = a0, a3 = a0;
    #pragma unroll 2
    for (int m = 0; m < Nz; m++) {
        float4 hv = h4[m * 16 + fq];
        float w0 = adj_s[(n0 + 0) * Nz + m];
        float w1 = adj_s[(n0 + 1) * Nz + m];
        float w2 = adj_s[(n0 + 2) * Nz + m];
        float w3 = adj_s[(n0 + 3) * Nz + m];
        a0.x += w0 * hv.x; a0.y += w0 * hv.y; a0.z += w0 * hv.z; a0.w += w0 * hv.w;
        a1.x += w1 * hv.x; a1.y += w1 * hv.y; a1.z += w1 * hv.z; a1.w += w1 * hv.w;
        a2.x += w2 * hv.x; a2.y += w2 * hv.y; a2.z += w2 * hv.z; a2.w += w2 * hv.w;
        a3.x += w3 * hv.x; a3.y += w3 * hv.y; a3.z += w3 * hv.z; a3.w += w3 * hv.w;
    }

    const int kc = fq >> 1;
    const int inner = (fq & 1) * 8;
    float4 vals[4] = {a0, a1, a2, a3};
    #pragma unroll
    for (int r = 0; r < 4; r++) {
        int mg = bt * Nz + n0 + r;
        int mtile = mg >> 7, row = mg & 127;
        uint8_t* block = dst + (size_t)(mtile * ncK + chunk) * 32768;
        uint32_t boff = (uint32_t)(row * 128 + ((kc ^ (row & 7)) << 4) + inner);
        uint32_t h0, l0, h1, l1;
        split_h2(vals[r].x, vals[r].y, h0, l0);
        split_h2(vals[r].z, vals[r].w, h1, l1);
        *(uint2*)(block + boff) = make_uint2(h0, h1);
        *(uint2*)(block + 16384 + boff) = make_uint2(l0, l1);
    }
}

// ---------------------------------------------------------------------------
// Temporal attention; output written as split image (feeds Wp GEMM).
// ---------------------------------------------------------------------------
#define QS 268

__global__ __launch_bounds__(512)
void attn_kernel(const float* __restrict__ q, const float* __restrict__ k,
                 const float* __restrict__ v, uint8_t* __restrict__ dst) {
    extern __shared__ float smf[];
    float* q_s = smf;
    float* k_s = q_s + Tz * QS;
    float* v_s = k_s + Tz * QS;
    float* p_s = v_s + Tz * QS;

    const int b = blockIdx.x / Nz;
    const int n = blockIdx.x % Nz;
    const size_t base = ((size_t)b * Tz * Nz + n) * Hz;
    const size_t tstride = (size_t)Nz * Hz;

    for (int i = threadIdx.x; i < Tz * Hz; i += blockDim.x) {
        int t = i >> 8; int hh = i & 255;
        q_s[t * QS + hh] = q[base + t * tstride + hh];
        k_s[t * QS + hh] = k[base + t * tstride + hh];
        v_s[t * QS + hh] = v[base + t * tstride + hh];
    }
    __syncthreads();

    if (threadIdx.x < Tz * Tz) {
        int t = threadIdx.x / Tz, s = threadIdx.x % Tz;
        const float4* q4 = (const float4*)(q_s + t * QS);
        const float4* k4 = (const float4*)(k_s + s * QS);
        float a0 = 0.f, a1 = 0.f;
        #pragma unroll 8
        for (int c = 0; c < 64; c += 2) {
            float4 qa = q4[c], ka = k4[c];
            float4 qb = q4[c + 1], kb = k4[c + 1];
            a0 += qa.x * ka.x + qa.y * ka.y + qa.z * ka.z + qa.w * ka.w;
            a1 += qb.x * kb.x + qb.y * kb.y + qb.z * kb.z + qb.w * kb.w;
        }
        p_s[t * 21 + s] = (a0 + a1) * 0.0625f;
    }
    __syncthreads();

    if (threadIdx.x < Tz) {
        int t = threadIdx.x;
        float mx = -1e30f;
        #pragma unroll
        for (int s = 0; s < Tz; s++) mx = fmaxf(mx, p_s[t * 21 + s]);
        float sum = 0.f;
        #pragma unroll
        for (int s = 0; s < Tz; s++) {
            float e = expf(p_s[t * 21 + s] - mx);
            p_s[t * 21 + s] = e; sum += e;
        }
        float inv = 1.f / sum;
        #pragma unroll
        for (int s = 0; s < Tz; s++) p_s[t * 21 + s] *= inv;
    }
    __syncthreads();

    for (int u = threadIdx.x; u < Tz * 32; u += 512) {
        int t = u >> 5, hgrp = u & 31;
        float acc[8] = {};
        #pragma unroll
        for (int s = 0; s < Tz; s++) {
            float p = p_s[t * 21 + s];
            const float4* vv = (const float4*)(v_s + s * QS + hgrp * 8);
            float4 va = vv[0], vb = vv[1];
            acc[0] += p * va.x; acc[1] += p * va.y; acc[2] += p * va.z; acc[3] += p * va.w;
            acc[4] += p * vb.x; acc[5] += p * vb.y; acc[6] += p * vb.z; acc[7] += p * vb.w;
        }
        int mg = b * Tz * Nz + t * Nz + n;
        int mtile = mg >> 7, row = mg & 127;
        int chunk = hgrp >> 3, kc = hgrp & 7;
        uint8_t* block = dst + (size_t)(mtile * 4 + chunk) * 32768;
        uint32_t boff = (uint32_t)(row * 128 + ((kc ^ (row & 7)) << 4));
        uint32_t hi[4], lo[4];
        split_h2(acc[0], acc[1], hi[0], lo[0]);
        split_h2(acc[2], acc[3], hi[1], lo[1]);
        split_h2(acc[4], acc[5], hi[2], lo[2]);
        split_h2(acc[6], acc[7], hi[3], lo[3]);
        *(uint4*)(block + boff) = make_uint4(hi[0], hi[1], hi[2], hi[3]);
        *(uint4*)(block + 16384 + boff) = make_uint4(lo[0], lo[1], lo[2], lo[3]);
    }
}

// ---------------------------------------------------------------------------
// launch
// ---------------------------------------------------------------------------
extern "C" void kernel_launch(void* const* d_in, const int* in_sizes, int n_in,
                              void* d_out, int out_size) {
    const float* x    = (const float*)d_in[0];
    const float* adj  = (const float*)d_in[1];
    const float* W0   = (const float*)d_in[2];
    const float* b0   = (const float*)d_in[3];
    const float* W1   = (const float*)d_in[4];
    const float* b1   = (const float*)d_in[5];
    const float* W2   = (const float*)d_in[6];
    const float* b2   = (const float*)d_in[7];
    const float* Wq   = (const float*)d_in[8];
    const float* bq   = (const float*)d_in[9];
    const float* Wk   = (const float*)d_in[10];
    const float* bk   = (const float*)d_in[11];
    const float* Wv   = (const float*)d_in[12];
    const float* bv   = (const float*)d_in[13];
    const float* Wp   = (const float*)d_in[14];
    const float* bp   = (const float*)d_in[15];
    const float* gamma = (const float*)d_in[16];
    const float* beta  = (const float*)d_in[17];
    float* out = (float*)d_out;

    float *ph, *pq, *pk, *pv, *pg;
    uint8_t *wp, *as1;
    cudaGetSymbolAddress((void**)&ph, g_h);
    cudaGetSymbolAddress((void**)&pg, g_g);
    cudaGetSymbolAddress((void**)&pq, g_q);
    cudaGetSymbolAddress((void**)&pk, g_k);
    cudaGetSymbolAddress((void**)&pv, g_v);
    cudaGetSymbolAddress((void**)&wp, g_wpack);
    cudaGetSymbolAddress((void**)&as1, g_asplit);
    uint8_t* as2 = (uint8_t*)pg;

    const int smem_adj  = (10000 + Nz * 64) * 4;          // 65.6 KB
    const int smem_attn = (3 * Tz * QS + Tz * 21) * 4;    // ~66 KB
    cudaFuncSetAttribute(adjmul_split, cudaFuncAttributeMaxDynamicSharedMemorySize, smem_adj);
    cudaFuncSetAttribute(attn_kernel,  cudaFuncAttributeMaxDynamicSharedMemorySize, smem_attn);
    cudaFuncSetAttribute(mma_gemm,     cudaFuncAttributeMaxDynamicSharedMemorySize, SMEM_GEMM);
    cudaFuncSetAttribute(qkv_gemm,     cudaFuncAttributeMaxDynamicSharedMemorySize, SMEM_GEMM);
    cudaFuncSetAttribute(gemm_ln,      cudaFuncAttributeMaxDynamicSharedMemorySize, SMEM_GLN);

    W7 ws;
    ws.w[0] = W0; ws.w[1] = W1; ws.w[2] = W2; ws.w[3] = Wq;
    ws.w[4] = Wk; ws.w[5] = Wv; ws.w[6] = Wp;
    pack_w_all<<<dim3(256, 7), 256>>>(ws, wp);

    const int BT = Bz * Tz;                 // 1280
    const int M = Bz * Tz * Nz;             // 128000
    const int GT = M / 128;                 // 1000

    // GCN layer 0 (F=64 -> H=256)
    adjmul_split<<<dim3(BT, 1), 512, smem_adj>>>(x, adj, as1, Fz);
    mma_gemm<<<GT, 512, SMEM_GEMM>>>(as1, wp + 0 * WPACK_STRIDE, b0, nullptr, ph, nullptr, Fz, 1);
    // GCN layer 1 (residual)
    adjmul_split<<<dim3(BT, 4), 512, smem_adj>>>(ph, adj, as1, Hz);
    mma_gemm<<<GT, 512, SMEM_GEMM>>>(as1, wp + 1 * WPACK_STRIDE, b1, ph, ph, nullptr, Hz, 1);
    // GCN layer 2 (residual) -> split image (feeds QKV)
    adjmul_split<<<dim3(BT, 4), 512, smem_adj>>>(ph, adj, as1, Hz);
    mma_gemm<<<GT, 512, SMEM_GEMM>>>(as1, wp + 2 * WPACK_STRIDE, b2, ph, nullptr, as2, Hz, 1);
    // Q, K, V fused launch — mat fastest-varying for A-tile L2 reuse
    qkv_gemm<<<dim3(3, GT), 512, SMEM_GEMM>>>(as2, wp, bq, bk, bv, pq, pk, pv);
    // attention -> split image (feeds Wp GEMM)
    attn_kernel<<<Bz * Nz, 512, smem_attn>>>(pq, pk, pv, as1);
    // output projection + fused LayerNorm -> final output
    gemm_ln<<<GT, 512, SMEM_GLN>>>(as1, wp + 6 * WPACK_STRIDE, bp, gamma, beta, out);
}